// round 1
// baseline (speedup 1.0000x reference)
#include <cuda_runtime.h>
#include <math.h>

// Problem constants
#define B_   256
#define T_   200
#define E_   100
#define H_   512
#define G4   2048          // 4*H
#define PAD_TOK 50000

typedef unsigned long long ull;

// ---------------- scratch (device globals; no allocation allowed) ----------------
__device__ float g_G[(size_t)T_ * B_ * G4];   // precomputed layer-0 input gates (incl. bias) ~419MB
__device__ float g_Gact[B_ * G4];             // per-step recurrent gate partial (full K sum)  2MB
__device__ float g_h0[2][B_ * H_];            // layer0 h ping-pong
__device__ float g_h1[2][B_ * H_];            // layer1 h ping-pong
__device__ float g_c0[B_ * H_];
__device__ float g_c1[B_ * H_];
__device__ float g_pool[B_ * H_];
__device__ int   g_tok[T_ * B_];              // tok[t*B + b] = X[b][t]
__device__ int   g_last[B_];

// ---------------- f32x2 packed-FMA helpers (sm_103a) ----------------
__device__ __forceinline__ ull ffma2(ull a, ull b, ull c) {
    ull d;
    asm("fma.rn.f32x2 %0, %1, %2, %3;" : "=l"(d) : "l"(a), "l"(b), "l"(c));
    return d;
}
__device__ __forceinline__ ull pack2(float x, float y) {
    ull r;
    asm("mov.b64 %0, {%1, %2};" : "=l"(r) : "f"(x), "f"(y));
    return r;
}
__device__ __forceinline__ float2 unpack2(ull v) {
    float2 f;
    asm("mov.b64 {%0, %1}, %2;" : "=f"(f.x), "=f"(f.y) : "l"(v));
    return f;
}

__device__ __forceinline__ float sigm(float x) { return 1.0f / (1.0f + expf(-x)); }

// ---------------- prep: transpose tokens + last non-pad position ----------------
__global__ void prep_kernel(const int* __restrict__ X) {
    __shared__ int red[256];
    int b = blockIdx.x;
    int t = threadIdx.x;
    int cand = -1;
    if (t < T_) {
        int tok = X[b * T_ + t];
        g_tok[t * B_ + b] = tok;
        if (tok != PAD_TOK) cand = t;
    }
    red[t] = cand;
    __syncthreads();
    for (int off = 128; off > 0; off >>= 1) {
        if (t < off) red[t] = max(red[t], red[t + off]);
        __syncthreads();
    }
    if (t == 0) g_last[b] = red[0];
}

// ---------------- init h/c/pool ----------------
__global__ void init_state() {
    int i = blockIdx.x * blockDim.x + threadIdx.x;  // 131072 = B*H
    g_c0[i] = 0.0f;
    g_c1[i] = 0.0f;
    g_h0[0][i] = 0.0f;
    g_h1[0][i] = 0.0f;
    g_pool[i] = -3.402823466e38f;                    // finfo(f32).min
}

// ---------------- batched embed-gather GEMM: G[m][j] = emb[tok[m]] . Wih0[j] + b0[j] ---
// M=51200, N=2048, K=100. Tile 128x128, BK=16, 256 threads, 8x8 micro (f32x2 pairs on j).
__global__ __launch_bounds__(256) void gemm_embed(
    const float* __restrict__ emb,
    const float* __restrict__ Wih,    // [2048][100]
    const float* __restrict__ bias)   // [2048]
{
    __shared__ float As[16][132];
    __shared__ float Bs[16][132];
    const int K = E_;
    int tid = threadIdx.x;
    int j0 = blockIdx.x * 128;
    int m0 = blockIdx.y * 128;
    int lk = tid & 15, lr = tid >> 4;
    int tx = tid & 15, ty = tid >> 4;
    ull acc[8][4];
    #pragma unroll
    for (int i = 0; i < 8; ++i)
        #pragma unroll
        for (int j = 0; j < 4; ++j) acc[i][j] = 0ull;

    for (int k0 = 0; k0 < K; k0 += 16) {
        #pragma unroll
        for (int p = 0; p < 8; ++p) {
            int r  = lr + p * 16;
            int gk = k0 + lk;
            float va = 0.0f, vb = 0.0f;
            if (gk < K) {
                va = emb[(size_t)g_tok[m0 + r] * E_ + gk];
                vb = Wih[(j0 + r) * K + gk];
            }
            As[lk][r] = va;
            Bs[lk][r] = vb;
        }
        __syncthreads();
        #pragma unroll
        for (int kk = 0; kk < 16; ++kk) {
            float4 a0 = *reinterpret_cast<const float4*>(&As[kk][ty * 8]);
            float4 a1 = *reinterpret_cast<const float4*>(&As[kk][ty * 8 + 4]);
            const ull* bp = reinterpret_cast<const ull*>(&Bs[kk][tx * 8]);
            ull b2[4];
            #pragma unroll
            for (int j = 0; j < 4; ++j) b2[j] = bp[j];
            float av[8] = {a0.x, a0.y, a0.z, a0.w, a1.x, a1.y, a1.z, a1.w};
            #pragma unroll
            for (int i = 0; i < 8; ++i) {
                ull a2 = pack2(av[i], av[i]);
                #pragma unroll
                for (int j = 0; j < 4; ++j) acc[i][j] = ffma2(a2, b2[j], acc[i][j]);
            }
        }
        __syncthreads();
    }
    #pragma unroll
    for (int i = 0; i < 8; ++i) {
        int m = m0 + ty * 8 + i;
        float* Crow = g_G + (size_t)m * G4 + j0 + tx * 8;
        #pragma unroll
        for (int j = 0; j < 4; ++j) {
            float2 v = unpack2(acc[i][j]);
            int jj = j0 + tx * 8 + j * 2;
            Crow[j * 2]     = v.x + bias[jj];
            Crow[j * 2 + 1] = v.y + bias[jj + 1];
        }
    }
}

// ---------------- per-step recurrent GEMM ----------------
// layer0: Gact[b][j] = h0_t . W_hh0[j]                     (K=512)
// layer1: Gact[b][j] = h1_t . W_hh1[j] + h0_{t}^out . W_ih1[j]  (K=1024)
// grid (32 j-tiles, 4 b-tiles), tile 64x64, 256 threads, 4x4 micro (f32x2 pairs on j).
__global__ __launch_bounds__(256) void step_gemm(
    int layer, int t,
    const float* __restrict__ WA,   // W_hh  (k < 512)
    const float* __restrict__ WB)   // W_ih1 (k >= 512), null for layer 0
{
    __shared__ float Hs[16][68];
    __shared__ float Ws[16][68];
    int tid = threadIdx.x;
    int j0 = blockIdx.x * 64;
    int b0 = blockIdx.y * 64;
    int par = t & 1;
    const float* hA = layer ? g_h1[par] : g_h0[par];
    const float* hB = g_h0[par ^ 1];   // layer-0 output of this step (layer 1 only)
    int K = layer ? 1024 : 512;
    int lk = tid & 15, lr = tid >> 4;  // loads: 16 rows/pass, 4 passes
    int tx = tid & 15, ty = tid >> 4;  // compute: 4 batch x 4 gates
    ull acc[4][2];
    #pragma unroll
    for (int i = 0; i < 4; ++i) { acc[i][0] = 0ull; acc[i][1] = 0ull; }

    for (int k0 = 0; k0 < K; k0 += 16) {
        const float* hsrc; const float* wsrc; int kb;
        if (k0 < 512) { hsrc = hA; wsrc = WA; kb = k0; }
        else          { hsrc = hB; wsrc = WB; kb = k0 - 512; }
        #pragma unroll
        for (int p = 0; p < 4; ++p) {
            int r = lr + p * 16;
            Hs[lk][r] = hsrc[(b0 + r) * H_ + kb + lk];
            Ws[lk][r] = wsrc[(j0 + r) * H_ + kb + lk];
        }
        __syncthreads();
        #pragma unroll
        for (int kk = 0; kk < 16; ++kk) {
            float4 av = *reinterpret_cast<const float4*>(&Hs[kk][ty * 4]);
            const ull* bp = reinterpret_cast<const ull*>(&Ws[kk][tx * 4]);
            ull bv0 = bp[0], bv1 = bp[1];
            ull a2;
            a2 = pack2(av.x, av.x); acc[0][0] = ffma2(a2, bv0, acc[0][0]); acc[0][1] = ffma2(a2, bv1, acc[0][1]);
            a2 = pack2(av.y, av.y); acc[1][0] = ffma2(a2, bv0, acc[1][0]); acc[1][1] = ffma2(a2, bv1, acc[1][1]);
            a2 = pack2(av.z, av.z); acc[2][0] = ffma2(a2, bv0, acc[2][0]); acc[2][1] = ffma2(a2, bv1, acc[2][1]);
            a2 = pack2(av.w, av.w); acc[3][0] = ffma2(a2, bv0, acc[3][0]); acc[3][1] = ffma2(a2, bv1, acc[3][1]);
        }
        __syncthreads();
    }
    #pragma unroll
    for (int i = 0; i < 4; ++i) {
        int b = b0 + ty * 4 + i;
        float* Crow = g_Gact + (size_t)b * G4 + j0 + tx * 4;
        float2 v0 = unpack2(acc[i][0]);
        float2 v1 = unpack2(acc[i][1]);
        Crow[0] = v0.x; Crow[1] = v0.y; Crow[2] = v1.x; Crow[3] = v1.y;
    }
}

// ---------------- per-step pointwise LSTM cell (+ fused maxpool on layer 1) ----------
__global__ void step_combine(int t, int layer, const float* __restrict__ bias1) {
    int gid = blockIdx.x * 256 + threadIdx.x;   // B*H = 131072
    int b = gid >> 9, u = gid & 511;
    int par = t & 1;
    float gate[4];
    #pragma unroll
    for (int q = 0; q < 4; ++q) {
        int j = q * 512 + u;
        float base = layer ? bias1[j] : g_G[((size_t)t * B_ + b) * G4 + j];
        gate[q] = base + g_Gact[(size_t)b * G4 + j];
    }
    float ig = sigm(gate[0]);
    float fg = sigm(gate[1]);
    float gg = tanhf(gate[2]);
    float og = sigm(gate[3]);
    float* cc = layer ? g_c1 : g_c0;
    float c = fg * cc[gid] + ig * gg;
    cc[gid] = c;
    float h = og * tanhf(c);
    if (layer) {
        g_h1[par ^ 1][gid] = h;
        if (t <= g_last[b]) g_pool[gid] = fmaxf(g_pool[gid], h);
    } else {
        g_h0[par ^ 1][gid] = h;
    }
}

// ---------------- final projection: logits = pool @ W_out^T + b_out ----------------
__global__ void final_kernel(const float* __restrict__ Wout,
                             const float* __restrict__ bout,
                             float* __restrict__ out) {
    int b = blockIdx.x, lane = threadIdx.x;
    float s0 = 0.f, s1 = 0.f, s2 = 0.f, s3 = 0.f, s4 = 0.f;
    for (int u = lane; u < H_; u += 32) {
        float p = g_pool[b * H_ + u];
        s0 += p * Wout[u];
        s1 += p * Wout[512 + u];
        s2 += p * Wout[1024 + u];
        s3 += p * Wout[1536 + u];
        s4 += p * Wout[2048 + u];
    }
    #pragma unroll
    for (int off = 16; off > 0; off >>= 1) {
        s0 += __shfl_down_sync(0xffffffffu, s0, off);
        s1 += __shfl_down_sync(0xffffffffu, s1, off);
        s2 += __shfl_down_sync(0xffffffffu, s2, off);
        s3 += __shfl_down_sync(0xffffffffu, s3, off);
        s4 += __shfl_down_sync(0xffffffffu, s4, off);
    }
    if (lane == 0) {
        out[b * 5 + 0] = s0 + bout[0];
        out[b * 5 + 1] = s1 + bout[1];
        out[b * 5 + 2] = s2 + bout[2];
        out[b * 5 + 3] = s3 + bout[3];
        out[b * 5 + 4] = s4 + bout[4];
    }
}

// ---------------- launch ----------------
extern "C" void kernel_launch(void* const* d_in, const int* in_sizes, int n_in,
                              void* d_out, int out_size) {
    (void)in_sizes; (void)n_in; (void)out_size;
    const int*   X     = (const int*)d_in[0];
    const float* emb   = (const float*)d_in[1];
    const float* W_ih0 = (const float*)d_in[2];
    const float* W_hh0 = (const float*)d_in[3];
    const float* b0    = (const float*)d_in[4];
    const float* W_ih1 = (const float*)d_in[5];
    const float* W_hh1 = (const float*)d_in[6];
    const float* b1    = (const float*)d_in[7];
    const float* W_out = (const float*)d_in[8];
    const float* b_out = (const float*)d_in[9];
    float* out = (float*)d_out;

    prep_kernel<<<B_, 256>>>(X);
    init_state<<<512, 256>>>();
    gemm_embed<<<dim3(G4 / 128, (T_ * B_) / 128), 256>>>(emb, W_ih0, b0);

    for (int t = 0; t < T_; ++t) {
        step_gemm<<<dim3(G4 / 64, B_ / 64), 256>>>(0, t, W_hh0, nullptr);
        step_combine<<<512, 256>>>(t, 0, nullptr);
        step_gemm<<<dim3(G4 / 64, B_ / 64), 256>>>(1, t, W_hh1, W_ih1);
        step_combine<<<512, 256>>>(t, 1, b1);
    }

    final_kernel<<<B_, 32>>>(W_out, b_out, out);
}